// round 12
// baseline (speedup 1.0000x reference)
#include <cuda_runtime.h>
#include <cstdint>

// Problem geometry
#define MROWS 8192          // 2*4096 rows of x
#define INSZ  4096          // input features
#define KF    512           // folded K dim (INSZ/8)
#define UNITS 4096          // output features

// Scratch (device globals: allocation-free rule)
__device__ __align__(256) int8_t g_xh[MROWS * KF];    // 4 MB  hi bytes of quantized xr
__device__ __align__(256) int8_t g_xl[MROWS * KF];    // 4 MB  lo bytes
__device__ __align__(256) int8_t g_w64[UNITS * KF];   // 2 MB  Wt[n][k] = 64*w
__device__ __align__(256) int8_t g_w1 [UNITS * KF];   // 2 MB  Wt[n][k] = w
__device__ __align__(256) float  g_scale[MROWS];      // per-row quant scale

// ---------------------------------------------------------------------------
// helpers
// ---------------------------------------------------------------------------
static __device__ __forceinline__ uint32_t smem_u32(const void* p) {
    uint32_t a;
    asm("{ .reg .u64 t; cvta.to.shared.u64 t, %1; cvt.u32.u64 %0, t; }"
        : "=r"(a) : "l"(p));
    return a;
}

static __device__ __forceinline__ void cp_async16(uint32_t dst, const void* src) {
    asm volatile("cp.async.cg.shared.global [%0], [%1], 16;"
                 :: "r"(dst), "l"(src) : "memory");
}
#define CP_COMMIT()  asm volatile("cp.async.commit_group;" ::: "memory")
#define CP_WAIT1()   asm volatile("cp.async.wait_group 1;" ::: "memory")

// ldmatrix (b16 form; byte-layout identical for s8-k32 fragments)
static __device__ __forceinline__ void ldsm4(uint32_t* r, uint32_t addr) {
    asm volatile("ldmatrix.sync.aligned.m8n8.x4.shared.b16 {%0,%1,%2,%3}, [%4];"
                 : "=r"(r[0]), "=r"(r[1]), "=r"(r[2]), "=r"(r[3]) : "r"(addr));
}
static __device__ __forceinline__ void ldsm2(uint32_t* r, uint32_t addr) {
    asm volatile("ldmatrix.sync.aligned.m8n8.x2.shared.b16 {%0,%1}, [%2];"
                 : "=r"(r[0]), "=r"(r[1]) : "r"(addr));
}

static __device__ __forceinline__ void mma16832_s8(int* d, const uint32_t* a,
                                                   uint32_t b0, uint32_t b1) {
    asm volatile(
        "mma.sync.aligned.m16n8k32.row.col.s32.s8.s8.s32 "
        "{%0,%1,%2,%3}, {%4,%5,%6,%7}, {%8,%9}, {%0,%1,%2,%3};"
        : "+r"(d[0]), "+r"(d[1]), "+r"(d[2]), "+r"(d[3])
        : "r"(a[0]), "r"(a[1]), "r"(a[2]), "r"(a[3]), "r"(b0), "r"(b1));
}

// ---------------------------------------------------------------------------
// Kernel 1: fold + quantize. One block (512 thr) per row m.
// ---------------------------------------------------------------------------
__global__ void __launch_bounds__(512)
fold_quant_kernel(const float* __restrict__ x) {
    __shared__ float red[16];
    const int m = blockIdx.x;
    const int q = threadIdx.x;
    const float* p = x + (size_t)m * INSZ + q;
    float v = 0.0f;
#pragma unroll
    for (int j = 0; j < 8; j++) v += p[j * 512];

    float a = fabsf(v);
#pragma unroll
    for (int o = 16; o > 0; o >>= 1)
        a = fmaxf(a, __shfl_xor_sync(0xFFFFFFFFu, a, o));
    if ((q & 31) == 0) red[q >> 5] = a;
    __syncthreads();
    float mx = red[0];
#pragma unroll
    for (int w = 1; w < 16; w++) mx = fmaxf(mx, red[w]);

    const float sq = (mx > 0.0f) ? (mx * (1.0f / 8191.0f)) : 1.0f;
    if (q == 0) g_scale[m] = sq;

    int qv = __float2int_rn(v / sq);          // in [-8191, 8191]
    int h  = qv >> 6;                         // [-128, 127]
    int l  = qv - (h << 6);                   // [0, 63]
    g_xh[(size_t)m * KF + q] = (int8_t)h;
    g_xl[(size_t)m * KF + q] = (int8_t)l;
}

// ---------------------------------------------------------------------------
// Kernel 2: transpose weights (int32 storage) -> two int8 operand matrices
// ---------------------------------------------------------------------------
__global__ void ktq_kernel(const int* __restrict__ kern) {
    __shared__ int tile[32][33];
    int n0 = blockIdx.x * 32;
    int k0 = blockIdx.y * 32;
    tile[threadIdx.y][threadIdx.x] =
        kern[(size_t)(k0 + threadIdx.y) * UNITS + n0 + threadIdx.x];
    __syncthreads();
    int n = n0 + threadIdx.y;
    int k = k0 + threadIdx.x;
    int w = tile[threadIdx.x][threadIdx.y];
    g_w64[(size_t)n * KF + k] = (int8_t)(w * 64);
    g_w1 [(size_t)n * KF + k] = (int8_t)w;
}

// ---------------------------------------------------------------------------
// Kernel 3: hybrid GEMM. Per 128x128 CTA tile:
//   cols   0-111: tensor (m16n8k32 s8 IMMA), 7 n8-groups per warp (2 warps n)
//   cols 112-127: dp4a on the cuda-core pipe, reading the SAME smem tiles
// acc = sum_k (h*(64w) + l*w) = q*w exactly; y = s_row * acc.
// 2-stage cp.async double buffer with wait_group 1 overlap.
// ---------------------------------------------------------------------------
#define BM 128
#define BN 128
#define NTEN 112                // tensor-covered columns per tile
#define BK 64                   // bytes (= k elements, int8)
#define RS 80                   // smem row stride in bytes
#define GEMM_THREADS 256
#define NITER 16                // 2 passes * (512/64)

__global__ void __launch_bounds__(GEMM_THREADS, 2)
gemm_kernel(float* __restrict__ y) {
    __shared__ __align__(16) int8_t As[2][BM * RS];   // 2 x 10 KB
    __shared__ __align__(16) int8_t Bs[2][BN * RS];   // 2 x 10 KB

    const int tid  = threadIdx.x;
    const int wid  = tid >> 5;
    const int lane = tid & 31;
    const int wm   = wid >> 1;          // 0..3  (m)
    const int wn   = wid & 1;           // 0..1  (n: 56 cols each)

    const int bn = blockIdx.x;          // 0..31
    const int bm = blockIdx.y;          // 0..63

    const int ch0 = tid;
    const int ch1 = tid + 256;
    const int r0c = ch0 >> 2, b0c = (ch0 & 3) * 16;
    const int r1c = ch1 >> 2, b1c = (ch1 & 3) * 16;

    uint32_t sA[2], sB[2];
#pragma unroll
    for (int s = 0; s < 2; s++) {
        sA[s] = smem_u32(As[s]);
        sB[s] = smem_u32(Bs[s]);
    }

    int acc[2][7][4];
#pragma unroll
    for (int i = 0; i < 2; i++)
#pragma unroll
        for (int j = 0; j < 7; j++)
#pragma unroll
            for (int k = 0; k < 4; k++) acc[i][j][k] = 0;

    int acc8[8];
#pragma unroll
    for (int c = 0; c < 8; c++) acc8[c] = 0;
    const int drow = tid & 127;          // dp4a row within tile
    const int dcb  = (tid >> 7) * 8;     // dp4a col base offset (0 or 8)

    auto load_tiles = [&](int it, int buf) {
        const bool lo = (it >= 8);
        const int8_t* ab = (lo ? g_xl  : g_xh ) + (size_t)bm * BM * KF;
        const int8_t* bb = (lo ? g_w1  : g_w64) + (size_t)bn * BN * KF;
        const int kc = (it & 7) * BK;
        uint32_t da = sA[buf];
        uint32_t db = sB[buf];
        cp_async16(da + (uint32_t)(r0c * RS + b0c), ab + (size_t)r0c * KF + kc + b0c);
        cp_async16(da + (uint32_t)(r1c * RS + b1c), ab + (size_t)r1c * KF + kc + b1c);
        cp_async16(db + (uint32_t)(r0c * RS + b0c), bb + (size_t)r0c * KF + kc + b0c);
        cp_async16(db + (uint32_t)(r1c * RS + b1c), bb + (size_t)r1c * KF + kc + b1c);
    };

    load_tiles(0, 0); CP_COMMIT();
    load_tiles(1, 1); CP_COMMIT();

    const int lj = lane >> 3;
    const int lr = lane & 7;

#pragma unroll 1
    for (int it = 0; it < NITER; it++) {
        CP_WAIT1();                      // tile `it` resident; `it+1` in flight
        __syncthreads();

        const int      buf    = it & 1;
        const uint32_t a_base = sA[buf];
        const uint32_t b_base = sB[buf];

#pragma unroll
        for (int ks = 0; ks < 2; ks++) {        // two k32 steps in BK=64
            const int kb = ks * 32;
            uint32_t af[2][4];
#pragma unroll
            for (int mi = 0; mi < 2; mi++) {
                int row = wm * 32 + mi * 16 + ((lj & 1) << 3) + lr;
                int col = kb + ((lj >> 1) << 4);
                ldsm4(af[mi], a_base + (uint32_t)(row * RS + col));
            }
            // B frags: pairs p=0..2 cover ni 0..5 (x4); ni=6 via x2
            uint32_t bfr[7][2];
#pragma unroll
            for (int p = 0; p < 3; p++) {
                int nr  = wn * 56 + (2 * p + (lj >> 1)) * 8 + lr;
                int col = kb + ((lj & 1) << 4);
                uint32_t t[4];
                ldsm4(t, b_base + (uint32_t)(nr * RS + col));
                bfr[2 * p][0]     = t[0];
                bfr[2 * p][1]     = t[1];
                bfr[2 * p + 1][0] = t[2];
                bfr[2 * p + 1][1] = t[3];
            }
            {
                // x2: lanes 0-15 supply addresses (j = lane>>3 in {0,1})
                int nr  = wn * 56 + 48 + lr;
                int col = kb + ((lj & 1) << 4);
                uint32_t t[2];
                ldsm2(t, b_base + (uint32_t)(nr * RS + col));
                bfr[6][0] = t[0];
                bfr[6][1] = t[1];
            }
#pragma unroll
            for (int mi = 0; mi < 2; mi++)
#pragma unroll
                for (int ni = 0; ni < 7; ni++)
                    mma16832_s8(acc[mi][ni], af[mi], bfr[ni][0], bfr[ni][1]);
        }

        // ---- dp4a side columns (tile cols 112..127), same smem tiles ----
        {
            const uint4* ap = (const uint4*)(As[buf] + drow * RS);
            uint4 aw[4];
#pragma unroll
            for (int w = 0; w < 4; w++) aw[w] = ap[w];
#pragma unroll
            for (int c = 0; c < 8; c++) {
                const uint4* bp =
                    (const uint4*)(Bs[buf] + (NTEN + dcb + c) * RS);
#pragma unroll
                for (int w = 0; w < 4; w++) {
                    uint4 bw = bp[w];
                    acc8[c] = __dp4a((int)aw[w].x, (int)bw.x, acc8[c]);
                    acc8[c] = __dp4a((int)aw[w].y, (int)bw.y, acc8[c]);
                    acc8[c] = __dp4a((int)aw[w].z, (int)bw.z, acc8[c]);
                    acc8[c] = __dp4a((int)aw[w].w, (int)bw.w, acc8[c]);
                }
            }
        }

        __syncthreads();
        if (it + 2 < NITER) {
            load_tiles(it + 2, buf);
            CP_COMMIT();
        }
    }

    // ---- tensor epilogue: y = s_row * float(acc), float2 stores ----
    const int g  = lane >> 2;
    const int c2 = (lane & 3) * 2;
    const size_t row0 = (size_t)bm * BM + wm * 32;
    const int    col0 = bn * BN + wn * 56;
#pragma unroll
    for (int mi = 0; mi < 2; mi++) {
        const size_t ra = row0 + mi * 16 + g;
        const size_t rb = ra + 8;
        const float  sa = g_scale[ra];
        const float  sb = g_scale[rb];
#pragma unroll
        for (int ni = 0; ni < 7; ni++) {
            float* p0 = y + ra * UNITS + col0 + ni * 8 + c2;
            float* p1 = y + rb * UNITS + col0 + ni * 8 + c2;
            *(float2*)p0 = make_float2(sa * (float)acc[mi][ni][0],
                                       sa * (float)acc[mi][ni][1]);
            *(float2*)p1 = make_float2(sb * (float)acc[mi][ni][2],
                                       sb * (float)acc[mi][ni][3]);
        }
    }

    // ---- dp4a epilogue: 8 consecutive cols per thread ----
    {
        const size_t rg = (size_t)bm * BM + drow;
        const float  s  = g_scale[rg];
        float* p = y + rg * UNITS + bn * BN + NTEN + dcb;
        float4 v0 = make_float4(s * (float)acc8[0], s * (float)acc8[1],
                                s * (float)acc8[2], s * (float)acc8[3]);
        float4 v1 = make_float4(s * (float)acc8[4], s * (float)acc8[5],
                                s * (float)acc8[6], s * (float)acc8[7]);
        *(float4*)p       = v0;
        *(float4*)(p + 4) = v1;
    }
}

// ---------------------------------------------------------------------------
// Launch — x is the larger buffer (33.5M vs 2.1M elements)
// ---------------------------------------------------------------------------
extern "C" void kernel_launch(void* const* d_in, const int* in_sizes, int n_in,
                              void* d_out, int out_size) {
    const float* x;
    const int*   kern;
    if (in_sizes[0] >= in_sizes[1]) {
        x    = (const float*)d_in[0];
        kern = (const int*)d_in[1];
    } else {
        kern = (const int*)d_in[0];
        x    = (const float*)d_in[1];
    }
    float* y = (float*)d_out;

    fold_quant_kernel<<<MROWS, 512>>>(x);
    ktq_kernel<<<dim3(UNITS / 32, KF / 32), dim3(32, 32)>>>(kern);
    gemm_kernel<<<dim3(UNITS / BN, MROWS / BM), GEMM_THREADS>>>(y);
}